// round 1
// baseline (speedup 1.0000x reference)
#include <cuda_runtime.h>
#include <cmath>

#define BB 2
#define LL 1024
#define DM 768
#define DI 1536
#define DS 16
#define DTR 48
#define XD 80            // DTR + 2*DS
#define ROWS (BB*LL)     // 2048

// ---------------- scratch (device globals; no allocation) ----------------
__device__ float g_xz[(size_t)ROWS * 2 * DI];      // 25.2 MB
__device__ float g_uc[2][(size_t)ROWS * DI];       // 25.2 MB
__device__ float g_xdbl[2][(size_t)ROWS * XD];     // 1.3 MB
__device__ float g_delta[2][(size_t)ROWS * DI];    // 25.2 MB
__device__ float g_y[2][(size_t)ROWS * DI];        // 25.2 MB
__device__ float g_ycomb[(size_t)ROWS * DI];       // 12.6 MB

// ---------------- SGEMM: C[M,N] = A[M,K] * B[N,K]^T (row-major) ----------
// 128x128 block tile, k-chunk 8, 8x8 per-thread microtile, 256 threads.
// All M,N multiples of 128 and K multiples of 8 for our shapes.
__global__ __launch_bounds__(256) void sgemm_nt(
    const float* __restrict__ A, const float* __restrict__ B,
    float* __restrict__ C, int M, int N, int K)
{
    __shared__ float As[8][132];
    __shared__ float Bs[8][132];
    int tid = threadIdx.x;
    int brow = blockIdx.y * 128;
    int bcol = blockIdx.x * 128;
    int lrow = tid >> 1;          // 0..127
    int lk   = (tid & 1) * 4;     // 0 or 4
    const float* Ag = A + (size_t)(brow + lrow) * K + lk;
    const float* Bg = B + (size_t)(bcol + lrow) * K + lk;
    int trow = (tid >> 4) << 3;
    int tcol = (tid & 15) << 3;
    float acc[8][8];
#pragma unroll
    for (int i = 0; i < 8; i++)
#pragma unroll
        for (int j = 0; j < 8; j++) acc[i][j] = 0.f;

    for (int k0 = 0; k0 < K; k0 += 8) {
        float4 av = *(const float4*)(Ag + k0);
        float4 bv = *(const float4*)(Bg + k0);
        __syncthreads();
        As[lk + 0][lrow] = av.x; As[lk + 1][lrow] = av.y;
        As[lk + 2][lrow] = av.z; As[lk + 3][lrow] = av.w;
        Bs[lk + 0][lrow] = bv.x; Bs[lk + 1][lrow] = bv.y;
        Bs[lk + 2][lrow] = bv.z; Bs[lk + 3][lrow] = bv.w;
        __syncthreads();
#pragma unroll
        for (int kk = 0; kk < 8; kk++) {
            float a[8], b[8];
            *(float4*)(a)     = *(const float4*)&As[kk][trow];
            *(float4*)(a + 4) = *(const float4*)&As[kk][trow + 4];
            *(float4*)(b)     = *(const float4*)&Bs[kk][tcol];
            *(float4*)(b + 4) = *(const float4*)&Bs[kk][tcol + 4];
#pragma unroll
            for (int i = 0; i < 8; i++)
#pragma unroll
                for (int j = 0; j < 8; j++)
                    acc[i][j] = fmaf(a[i], b[j], acc[i][j]);
        }
    }
#pragma unroll
    for (int i = 0; i < 8; i++) {
        float* Cp = C + (size_t)(brow + trow + i) * N + bcol + tcol;
        *(float4*)(Cp)     = make_float4(acc[i][0], acc[i][1], acc[i][2], acc[i][3]);
        *(float4*)(Cp + 4) = make_float4(acc[i][4], acc[i][5], acc[i][6], acc[i][7]);
    }
}

// ---------------- causal depthwise conv (K=4) + SiLU, both directions ----
// dir 1 works entirely in reversed-L coordinates: u_rev(j) = u(L-1-j).
__global__ void conv_silu_kernel(const float* __restrict__ cw_f, const float* __restrict__ cb_f,
                                 const float* __restrict__ cw_r, const float* __restrict__ cb_r)
{
    int idx = blockIdx.x * blockDim.x + threadIdx.x;
    if (idx >= 2 * ROWS * DI) return;
    int c  = idx % DI;
    int rl = idx / DI;
    int l  = rl % LL;
    int b  = (rl / LL) % BB;
    int dir = rl / (LL * BB);
    const float* cw = dir ? cw_r : cw_f;
    const float* cb = dir ? cb_r : cb_f;
    float s = cb[c];
#pragma unroll
    for (int k = 0; k < 4; k++) {
        int j = l - 3 + k;                 // index in this direction's coords
        if (j >= 0) {
            int lsrc = dir ? (LL - 1 - j) : j;
            s += cw[c * 4 + k] * g_xz[(size_t)(b * LL + lsrc) * (2 * DI) + c];
        }
    }
    float sig = 1.f / (1.f + __expf(-s));
    g_uc[dir][(size_t)(b * LL + l) * DI + c] = s * sig;
}

// ---------------- x_proj: xdbl[2048,80] = uc[2048,1536] @ W[80,1536]^T ---
// block: 32 rows x 80 cols, 256 threads, thread tile 2x5, k-chunk 64
__global__ __launch_bounds__(256) void xproj_kernel(int dir, const float* __restrict__ W)
{
    __shared__ float us[32][65];
    __shared__ float ws[80][65];
    int tid = threadIdx.x;
    int row0 = blockIdx.x * 32;
    const float* U = g_uc[dir] + (size_t)row0 * DI;
    int tx = tid & 15;    // col group: cols tx*5 .. tx*5+4
    int ty = tid >> 4;    // row group: rows ty*2, ty*2+1
    float acc[2][5] = {};
    for (int k0 = 0; k0 < DI; k0 += 64) {
        __syncthreads();
#pragma unroll
        for (int i = 0; i < 2; i++) {       // 32x64 = 512 float4
            int e = tid + i * 256;
            int r = e >> 4; int kq = (e & 15) << 2;
            float4 v = *(const float4*)(U + (size_t)r * DI + k0 + kq);
            us[r][kq + 0] = v.x; us[r][kq + 1] = v.y; us[r][kq + 2] = v.z; us[r][kq + 3] = v.w;
        }
#pragma unroll
        for (int i = 0; i < 5; i++) {       // 80x64 = 1280 float4
            int e = tid + i * 256;
            int r = e >> 4; int kq = (e & 15) << 2;
            float4 v = *(const float4*)(W + (size_t)r * DI + k0 + kq);
            ws[r][kq + 0] = v.x; ws[r][kq + 1] = v.y; ws[r][kq + 2] = v.z; ws[r][kq + 3] = v.w;
        }
        __syncthreads();
#pragma unroll 8
        for (int k = 0; k < 64; k++) {
            float a0 = us[ty * 2][k], a1 = us[ty * 2 + 1][k];
#pragma unroll
            for (int j = 0; j < 5; j++) {
                float w = ws[tx * 5 + j][k];
                acc[0][j] = fmaf(a0, w, acc[0][j]);
                acc[1][j] = fmaf(a1, w, acc[1][j]);
            }
        }
    }
    float* O = g_xdbl[dir] + (size_t)row0 * XD;
#pragma unroll
    for (int i = 0; i < 2; i++)
#pragma unroll
        for (int j = 0; j < 5; j++)
            O[(size_t)(ty * 2 + i) * XD + tx * 5 + j] = acc[i][j];
}

// ---------------- dt proj + softplus: delta[2048,1536] ------------------
// block: 32 rows x 256 channels; per-thread: one channel, 48 weights in regs
__global__ __launch_bounds__(256) void dtproj_kernel(int dir, const float* __restrict__ Wdt,
                                                     const float* __restrict__ bdt)
{
    __shared__ float xs[32][DTR];
    int tid = threadIdx.x;
    int row0 = blockIdx.x * 32;
    int c = blockIdx.y * 256 + tid;
    for (int e = tid; e < 32 * DTR; e += 256) {
        int r = e / DTR, j = e % DTR;
        xs[r][j] = g_xdbl[dir][(size_t)(row0 + r) * XD + j];
    }
    __syncthreads();
    float w[DTR];
#pragma unroll
    for (int j = 0; j < DTR; j++) w[j] = Wdt[(size_t)c * DTR + j];
    float bias = bdt[c];
    for (int r = 0; r < 32; r++) {
        float acc = bias;
#pragma unroll
        for (int j = 0; j < DTR; j++) acc = fmaf(xs[r][j], w[j], acc);
        float d = (acc > 20.f) ? acc : log1pf(__expf(acc));
        g_delta[dir][(size_t)(row0 + r) * DI + c] = d;
    }
}

// ---------------- selective scan --------------------------------------
// Half-warp (16 lanes = 16 states) per channel; 2 channels per warp.
// h-recurrence critical chain is a single FFMA per step (exp is off-chain).
__global__ __launch_bounds__(256) void scan_kernel(
    const float* __restrict__ Alog_f, const float* __restrict__ D_f,
    const float* __restrict__ Alog_r, const float* __restrict__ D_r)
{
    int tid = threadIdx.x;
    int dir = blockIdx.z;
    int b = blockIdx.y;
    int c = blockIdx.x * 16 + (tid >> 4);
    int s = tid & 15;
    const float* Alog = dir ? Alog_r : Alog_f;
    const float* Dp   = dir ? D_r : D_f;
    float a  = -__expf(Alog[c * DS + s]);
    float Dv = Dp[c];
    const float* dlt = g_delta[dir] + (size_t)(b * LL) * DI + c;
    const float* uu  = g_uc[dir]    + (size_t)(b * LL) * DI + c;
    const float* xd  = g_xdbl[dir]  + (size_t)(b * LL) * XD;
    float* yo        = g_y[dir]     + (size_t)(b * LL) * DI + c;
    float h = 0.f;
#pragma unroll 4
    for (int t = 0; t < LL; t++) {
        float d  = dlt[(size_t)t * DI];
        float uv = uu[(size_t)t * DI];
        float Bv = xd[(size_t)t * XD + DTR + s];
        float Cv = xd[(size_t)t * XD + DTR + DS + s];
        float dA = __expf(d * a);
        h = fmaf(dA, h, d * Bv * uv);
        float p = h * Cv;
        p += __shfl_xor_sync(0xffffffffu, p, 1);
        p += __shfl_xor_sync(0xffffffffu, p, 2);
        p += __shfl_xor_sync(0xffffffffu, p, 4);
        p += __shfl_xor_sync(0xffffffffu, p, 8);
        if (s == 0) yo[(size_t)t * DI] = fmaf(uv, Dv, p);
    }
}

// ---------------- combine + gate: (y_f + flip(y_r)) * silu(z) -----------
__global__ void combine_kernel()
{
    int idx = blockIdx.x * blockDim.x + threadIdx.x;
    if (idx >= ROWS * DI) return;
    int c = idx % DI;
    int l = (idx / DI) % LL;
    int b = idx / (DI * LL);
    float yf = g_y[0][idx];
    float yr = g_y[1][(size_t)(b * LL + (LL - 1 - l)) * DI + c];
    float z  = g_xz[(size_t)(b * LL + l) * (2 * DI) + DI + c];
    float sig = 1.f / (1.f + __expf(-z));
    g_ycomb[idx] = (yf + yr) * (z * sig);
}

// ---------------- launch -------------------------------------------------
extern "C" void kernel_launch(void* const* d_in, const int* in_sizes, int n_in,
                              void* d_out, int out_size)
{
    const float* x      = (const float*)d_in[0];
    const float* in_w   = (const float*)d_in[1];
    const float* out_w  = (const float*)d_in[2];
    const float* cw_f   = (const float*)d_in[3];
    const float* cb_f   = (const float*)d_in[4];
    const float* xp_f   = (const float*)d_in[5];
    const float* dtw_f  = (const float*)d_in[6];
    const float* dtb_f  = (const float*)d_in[7];
    const float* Alog_f = (const float*)d_in[8];
    const float* D_f    = (const float*)d_in[9];
    const float* cw_r   = (const float*)d_in[10];
    const float* cb_r   = (const float*)d_in[11];
    const float* xp_r   = (const float*)d_in[12];
    const float* dtw_r  = (const float*)d_in[13];
    const float* dtb_r  = (const float*)d_in[14];
    const float* Alog_r = (const float*)d_in[15];
    const float* D_r    = (const float*)d_in[16];
    float* out = (float*)d_out;

    float* xz;    cudaGetSymbolAddress((void**)&xz, g_xz);
    float* ycomb; cudaGetSymbolAddress((void**)&ycomb, g_ycomb);

    // 1. xz = x @ in_w^T  (shared between both directions)
    sgemm_nt<<<dim3((2 * DI) / 128, ROWS / 128), 256>>>(x, in_w, xz, ROWS, 2 * DI, DM);
    // 2. conv + silu for both directions (reverse in flipped coords)
    conv_silu_kernel<<<(2 * ROWS * DI + 255) / 256, 256>>>(cw_f, cb_f, cw_r, cb_r);
    // 3. x_proj per direction
    xproj_kernel<<<ROWS / 32, 256>>>(0, xp_f);
    xproj_kernel<<<ROWS / 32, 256>>>(1, xp_r);
    // 4. dt projection + softplus per direction
    dtproj_kernel<<<dim3(ROWS / 32, DI / 256), 256>>>(0, dtw_f, dtb_f);
    dtproj_kernel<<<dim3(ROWS / 32, DI / 256), 256>>>(1, dtw_r, dtb_r);
    // 5. selective scan, both directions in one launch
    scan_kernel<<<dim3(DI / 16, BB, 2), 256>>>(Alog_f, D_f, Alog_r, D_r);
    // 6. combine (+flip) and gate
    combine_kernel<<<(ROWS * DI + 255) / 256, 256>>>();
    // 7. out = ycomb @ out_w^T  (single GEMM thanks to linearity)
    sgemm_nt<<<dim3(DM / 128, ROWS / 128), 256>>>(ycomb, out_w, out, ROWS, DM, DI);
}

// round 3
// speedup vs baseline: 1.0572x; 1.0572x over previous
#include <cuda_runtime.h>
#include <cuda_bf16.h>
#include <cstdint>
#include <cmath>

#define BB 2
#define LL 1024
#define DM 768
#define DI 1536
#define DS 16
#define DTR 48
#define XD 80            // DTR + 2*DS
#define ROWS (BB*LL)     // 2048
#define KSPLIT 6

// ================= helpers =================================================
__device__ __forceinline__ uint32_t smem_to_u32(const void* p) {
    uint32_t a;
    asm("{ .reg .u64 t; cvta.to.shared.u64 t, %1; cvt.u32.u64 %0, t; }" : "=r"(a) : "l"(p));
    return a;
}
__device__ __forceinline__ void cpasync16(uint32_t dst, const void* src) {
    asm volatile("cp.async.cg.shared.global [%0], [%1], 16;" :: "r"(dst), "l"(src));
}
#define CP_COMMIT() asm volatile("cp.async.commit_group;" ::: "memory")
#define CP_WAIT1()  asm volatile("cp.async.wait_group 1;" ::: "memory")

__device__ __forceinline__ void ldsm4(uint32_t* r, uint32_t addr) {
    asm volatile("ldmatrix.sync.aligned.m8n8.x4.shared.b16 {%0,%1,%2,%3}, [%4];"
        : "=r"(r[0]), "=r"(r[1]), "=r"(r[2]), "=r"(r[3]) : "r"(addr));
}
__device__ __forceinline__ void mma_bf16(float* c, const uint32_t* a, uint32_t b0, uint32_t b1) {
    asm volatile("mma.sync.aligned.m16n8k16.row.col.f32.bf16.bf16.f32 "
        "{%0,%1,%2,%3}, {%4,%5,%6,%7}, {%8,%9}, {%0,%1,%2,%3};"
        : "+f"(c[0]), "+f"(c[1]), "+f"(c[2]), "+f"(c[3])
        : "r"(a[0]), "r"(a[1]), "r"(a[2]), "r"(a[3]), "r"(b0), "r"(b1));
}

// ================= scratch (device globals; no allocation) =================
__device__ float g_xz[(size_t)ROWS * 2 * DI];
__device__ float g_uc[2][(size_t)ROWS * DI];
__device__ float g_xdbl[2][(size_t)ROWS * XD];
__device__ float g_xpart[2][KSPLIT][(size_t)ROWS * XD];
__device__ float g_delta[2][(size_t)ROWS * DI];
__device__ float g_y[2][(size_t)ROWS * DI];
// bf16 hi/lo operand buffers
__device__ __nv_bfloat16 g_ah[(size_t)ROWS * DM];
__device__ __nv_bfloat16 g_al[(size_t)ROWS * DM];
__device__ __nv_bfloat16 g_w1h[(size_t)(2 * DI) * DM];
__device__ __nv_bfloat16 g_w1l[(size_t)(2 * DI) * DM];
__device__ __nv_bfloat16 g_ych[(size_t)ROWS * DI];
__device__ __nv_bfloat16 g_ycl[(size_t)ROWS * DI];
__device__ __nv_bfloat16 g_w2h[(size_t)DM * DI];
__device__ __nv_bfloat16 g_w2l[(size_t)DM * DI];

// ================= fp32 -> bf16 hi/lo split ================================
__global__ void cvt_split(const float* __restrict__ s, __nv_bfloat16* __restrict__ h,
                          __nv_bfloat16* __restrict__ l, int n4)
{
    int i = blockIdx.x * blockDim.x + threadIdx.x;
    if (i >= n4) return;
    float4 v = ((const float4*)s)[i];
    __nv_bfloat16 h0 = __float2bfloat16(v.x), h1 = __float2bfloat16(v.y);
    __nv_bfloat16 h2 = __float2bfloat16(v.z), h3 = __float2bfloat16(v.w);
    __nv_bfloat16 l0 = __float2bfloat16(v.x - __bfloat162float(h0));
    __nv_bfloat16 l1 = __float2bfloat16(v.y - __bfloat162float(h1));
    __nv_bfloat16 l2 = __float2bfloat16(v.z - __bfloat162float(h2));
    __nv_bfloat16 l3 = __float2bfloat16(v.w - __bfloat162float(h3));
    ((__nv_bfloat162*)h)[2 * i]     = __nv_bfloat162(h0, h1);
    ((__nv_bfloat162*)h)[2 * i + 1] = __nv_bfloat162(h2, h3);
    ((__nv_bfloat162*)l)[2 * i]     = __nv_bfloat162(l0, l1);
    ((__nv_bfloat162*)l)[2 * i + 1] = __nv_bfloat162(l2, l3);
}

// ================= HMMA GEMM: C[M,N] = A*B^T, bf16 hi/lo 3-product =========
// 128x128 CTA tile, K-chunk 32, 8 warps of 64x32, cp.async double buffer.
#define KT 32
#define RB 40                      // padded row length in bf16 (80 bytes)
#define TILE_B (128 * RB * 2)      // 10240 bytes per tile
#define STAGE_B (4 * TILE_B)       // Ah, Al, Bh, Bl
#define GEMM_SMEM (2 * STAGE_B)    // 81920 bytes

__global__ void __launch_bounds__(256, 1) gemm_bf3(
    const __nv_bfloat16* __restrict__ Ah, const __nv_bfloat16* __restrict__ Al,
    const __nv_bfloat16* __restrict__ Bh, const __nv_bfloat16* __restrict__ Bl,
    float* __restrict__ C, int M, int N, int K)
{
    extern __shared__ char smem[];
    uint32_t sb = smem_to_u32(smem);
    int tid = threadIdx.x;
    int lane = tid & 31, wid = tid >> 5;
    int wm = (wid & 1) * 64, wn = (wid >> 1) * 32;
    int m0 = blockIdx.y * 128, n0 = blockIdx.x * 128;
    const int NC = K / KT;

    float acc[4][4][4];
#pragma unroll
    for (int a = 0; a < 4; a++)
#pragma unroll
        for (int b = 0; b < 4; b++)
#pragma unroll
            for (int c = 0; c < 4; c++) acc[a][b][c] = 0.f;

    // stage loader: 4 tiles x 512 x 16B, 2 cp.async per thread per tile
#define LOAD_STAGE(IT, S)                                                          \
    do {                                                                           \
        uint32_t stg_ = sb + (S) * STAGE_B;                                        \
        int kof_ = (IT) * KT;                                                      \
        _Pragma("unroll")                                                          \
        for (int i_ = 0; i_ < 2; i_++) {                                           \
            int v_ = tid + i_ * 256;                                               \
            int r_ = v_ >> 2, c_ = v_ & 3;                                         \
            uint32_t d_ = stg_ + r_ * (RB * 2) + c_ * 16;                          \
            cpasync16(d_,              Ah + (size_t)(m0 + r_) * K + kof_ + c_ * 8);\
            cpasync16(d_ + TILE_B,     Al + (size_t)(m0 + r_) * K + kof_ + c_ * 8);\
            cpasync16(d_ + 2 * TILE_B, Bh + (size_t)(n0 + r_) * K + kof_ + c_ * 8);\
            cpasync16(d_ + 3 * TILE_B, Bl + (size_t)(n0 + r_) * K + kof_ + c_ * 8);\
        }                                                                          \
    } while (0)

    LOAD_STAGE(0, 0); CP_COMMIT();
    LOAD_STAGE(1, 1); CP_COMMIT();

    for (int it = 0; it < NC; it++) {
        int s = it & 1;
        CP_WAIT1();
        __syncthreads();
        uint32_t stg = sb + s * STAGE_B;
#pragma unroll
        for (int ks = 0; ks < 2; ks++) {
            uint32_t aH[4][4], aL[4][4];
            int arow = wm + ((lane >> 3) & 1) * 8 + (lane & 7);
            int acol = ks * 16 + (lane >> 4) * 8;
#pragma unroll
            for (int mt = 0; mt < 4; mt++) {
                uint32_t off = ((uint32_t)(arow + mt * 16) * RB + acol) * 2;
                ldsm4(aH[mt], stg + off);
                ldsm4(aL[mt], stg + TILE_B + off);
            }
            int brow = wn + (lane >> 4) * 8 + (lane & 7);
            int bcol = ks * 16 + ((lane >> 3) & 1) * 8;
#pragma unroll
            for (int p = 0; p < 2; p++) {
                uint32_t bh[4], bl[4];
                uint32_t off = ((uint32_t)(brow + p * 16) * RB + bcol) * 2;
                ldsm4(bh, stg + 2 * TILE_B + off);
                ldsm4(bl, stg + 3 * TILE_B + off);
#pragma unroll
                for (int mt = 0; mt < 4; mt++) {
                    mma_bf16(acc[mt][2 * p],     aH[mt], bh[0], bh[1]);
                    mma_bf16(acc[mt][2 * p],     aH[mt], bl[0], bl[1]);
                    mma_bf16(acc[mt][2 * p],     aL[mt], bh[0], bh[1]);
                    mma_bf16(acc[mt][2 * p + 1], aH[mt], bh[2], bh[3]);
                    mma_bf16(acc[mt][2 * p + 1], aH[mt], bl[2], bl[3]);
                    mma_bf16(acc[mt][2 * p + 1], aL[mt], bh[2], bh[3]);
                }
            }
        }
        __syncthreads();
        if (it + 2 < NC) LOAD_STAGE(it + 2, s);
        CP_COMMIT();
    }

    int g = lane >> 2, tg = lane & 3;
#pragma unroll
    for (int mt = 0; mt < 4; mt++)
#pragma unroll
        for (int nt = 0; nt < 4; nt++) {
            int row = m0 + wm + mt * 16 + g;
            int col = n0 + wn + nt * 8 + tg * 2;
            *(float2*)&C[(size_t)row * N + col] =
                make_float2(acc[mt][nt][0], acc[mt][nt][1]);
            *(float2*)&C[(size_t)(row + 8) * N + col] =
                make_float2(acc[mt][nt][2], acc[mt][nt][3]);
        }
#undef LOAD_STAGE
}

// ================= causal depthwise conv (K=4) + SiLU, both dirs ==========
__global__ void conv_silu_kernel(const float* __restrict__ cw_f, const float* __restrict__ cb_f,
                                 const float* __restrict__ cw_r, const float* __restrict__ cb_r)
{
    int idx = blockIdx.x * blockDim.x + threadIdx.x;
    if (idx >= 2 * ROWS * DI) return;
    int c = idx % DI;
    int rl = idx / DI;
    int l = rl % LL;
    int b = (rl / LL) % BB;
    int dir = rl / (LL * BB);
    const float* cw = dir ? cw_r : cw_f;
    const float* cb = dir ? cb_r : cb_f;
    float s = cb[c];
#pragma unroll
    for (int k = 0; k < 4; k++) {
        int j = l - 3 + k;
        if (j >= 0) {
            int lsrc = dir ? (LL - 1 - j) : j;
            s += cw[c * 4 + k] * g_xz[(size_t)(b * LL + lsrc) * (2 * DI) + c];
        }
    }
    float sig = 1.f / (1.f + __expf(-s));
    g_uc[dir][(size_t)(b * LL + l) * DI + c] = s * sig;
}

// ================= x_proj split-K (deterministic, partials buffer) =========
__global__ __launch_bounds__(256) void xproj_splitk(const float* __restrict__ Wf,
                                                    const float* __restrict__ Wr)
{
    __shared__ float us[32][65];
    __shared__ float ws[80][65];
    int tid = threadIdx.x;
    int dir = blockIdx.z;
    int row0 = blockIdx.x * 32;
    int kb = blockIdx.y;
    int kbase = kb * 256;
    const float* W = dir ? Wr : Wf;
    const float* U = g_uc[dir] + (size_t)row0 * DI;
    int tx = tid & 15;
    int ty = tid >> 4;
    float acc[2][5] = {};
    for (int kc = 0; kc < 256; kc += 64) {
        int k0 = kbase + kc;
        __syncthreads();
#pragma unroll
        for (int i = 0; i < 2; i++) {
            int e = tid + i * 256;
            int r = e >> 4; int kq = (e & 15) << 2;
            float4 v = *(const float4*)(U + (size_t)r * DI + k0 + kq);
            us[r][kq + 0] = v.x; us[r][kq + 1] = v.y; us[r][kq + 2] = v.z; us[r][kq + 3] = v.w;
        }
#pragma unroll
        for (int i = 0; i < 5; i++) {
            int e = tid + i * 256;
            int r = e >> 4; int kq = (e & 15) << 2;
            float4 v = *(const float4*)(W + (size_t)r * DI + k0 + kq);
            ws[r][kq + 0] = v.x; ws[r][kq + 1] = v.y; ws[r][kq + 2] = v.z; ws[r][kq + 3] = v.w;
        }
        __syncthreads();
#pragma unroll 8
        for (int k = 0; k < 64; k++) {
            float a0 = us[ty * 2][k], a1 = us[ty * 2 + 1][k];
#pragma unroll
            for (int j = 0; j < 5; j++) {
                float w = ws[tx * 5 + j][k];
                acc[0][j] = fmaf(a0, w, acc[0][j]);
                acc[1][j] = fmaf(a1, w, acc[1][j]);
            }
        }
    }
    float* O = g_xpart[dir][kb] + (size_t)row0 * XD;
#pragma unroll
    for (int i = 0; i < 2; i++)
#pragma unroll
        for (int j = 0; j < 5; j++)
            O[(size_t)(ty * 2 + i) * XD + tx * 5 + j] = acc[i][j];
}

__global__ void xreduce()
{
    int i = blockIdx.x * blockDim.x + threadIdx.x;
    if (i >= 2 * ROWS * XD) return;
    int dir = i / (ROWS * XD);
    int off = i % (ROWS * XD);
    float s = 0.f;
#pragma unroll
    for (int k = 0; k < KSPLIT; k++) s += g_xpart[dir][k][off];
    g_xdbl[dir][off] = s;
}

// ================= dt proj + softplus ======================================
__global__ __launch_bounds__(256) void dtproj_kernel(
    const float* __restrict__ Wf, const float* __restrict__ bf,
    const float* __restrict__ Wr, const float* __restrict__ br)
{
    __shared__ float xs[32][DTR];
    int tid = threadIdx.x;
    int dir = blockIdx.z;
    int row0 = blockIdx.x * 32;
    int c = blockIdx.y * 256 + tid;
    const float* Wdt = dir ? Wr : Wf;
    const float* bdt = dir ? br : bf;
    for (int e = tid; e < 32 * DTR; e += 256) {
        int r = e / DTR, j = e % DTR;
        xs[r][j] = g_xdbl[dir][(size_t)(row0 + r) * XD + j];
    }
    __syncthreads();
    float w[DTR];
#pragma unroll
    for (int j = 0; j < DTR; j++) w[j] = Wdt[(size_t)c * DTR + j];
    float bias = bdt[c];
    for (int r = 0; r < 32; r++) {
        float acc = bias;
#pragma unroll
        for (int j = 0; j < DTR; j++) acc = fmaf(xs[r][j], w[j], acc);
        float d = (acc > 20.f) ? acc : log1pf(__expf(acc));
        g_delta[dir][(size_t)(row0 + r) * DI + c] = d;
    }
}

// ================= selective scan ==========================================
__global__ __launch_bounds__(256) void scan_kernel(
    const float* __restrict__ Alog_f, const float* __restrict__ D_f,
    const float* __restrict__ Alog_r, const float* __restrict__ D_r)
{
    int tid = threadIdx.x;
    int dir = blockIdx.z;
    int b = blockIdx.y;
    int c = blockIdx.x * 16 + (tid >> 4);
    int s = tid & 15;
    const float* Alog = dir ? Alog_r : Alog_f;
    const float* Dp   = dir ? D_r : D_f;
    float a  = -__expf(Alog[c * DS + s]);
    float Dv = Dp[c];
    const float* dlt = g_delta[dir] + (size_t)(b * LL) * DI + c;
    const float* uu  = g_uc[dir]    + (size_t)(b * LL) * DI + c;
    const float* xd  = g_xdbl[dir]  + (size_t)(b * LL) * XD;
    float* yo        = g_y[dir]     + (size_t)(b * LL) * DI + c;
    float h = 0.f;
#pragma unroll 4
    for (int t = 0; t < LL; t++) {
        float d  = dlt[(size_t)t * DI];
        float uv = uu[(size_t)t * DI];
        float Bv = xd[(size_t)t * XD + DTR + s];
        float Cv = xd[(size_t)t * XD + DTR + DS + s];
        float dA = __expf(d * a);
        h = fmaf(dA, h, d * Bv * uv);
        float p = h * Cv;
        p += __shfl_xor_sync(0xffffffffu, p, 1);
        p += __shfl_xor_sync(0xffffffffu, p, 2);
        p += __shfl_xor_sync(0xffffffffu, p, 4);
        p += __shfl_xor_sync(0xffffffffu, p, 8);
        if (s == 0) yo[(size_t)t * DI] = fmaf(uv, Dv, p);
    }
}

// ================= combine + gate -> bf16 hi/lo ============================
__global__ void combine_kernel()
{
    int idx = blockIdx.x * blockDim.x + threadIdx.x;
    if (idx >= ROWS * DI) return;
    int c = idx % DI;
    int l = (idx / DI) % LL;
    int b = idx / (DI * LL);
    float yf = g_y[0][idx];
    float yr = g_y[1][(size_t)(b * LL + (LL - 1 - l)) * DI + c];
    float z  = g_xz[(size_t)(b * LL + l) * (2 * DI) + DI + c];
    float sig = 1.f / (1.f + __expf(-z));
    float v = (yf + yr) * (z * sig);
    __nv_bfloat16 h = __float2bfloat16(v);
    g_ych[idx] = h;
    g_ycl[idx] = __float2bfloat16(v - __bfloat162float(h));
}

// ================= launch ==================================================
extern "C" void kernel_launch(void* const* d_in, const int* in_sizes, int n_in,
                              void* d_out, int out_size)
{
    const float* x      = (const float*)d_in[0];
    const float* in_w   = (const float*)d_in[1];
    const float* out_w  = (const float*)d_in[2];
    const float* cw_f   = (const float*)d_in[3];
    const float* cb_f   = (const float*)d_in[4];
    const float* xp_f   = (const float*)d_in[5];
    const float* dtw_f  = (const float*)d_in[6];
    const float* dtb_f  = (const float*)d_in[7];
    const float* Alog_f = (const float*)d_in[8];
    const float* D_f    = (const float*)d_in[9];
    const float* cw_r   = (const float*)d_in[10];
    const float* cb_r   = (const float*)d_in[11];
    const float* xp_r   = (const float*)d_in[12];
    const float* dtw_r  = (const float*)d_in[13];
    const float* dtb_r  = (const float*)d_in[14];
    const float* Alog_r = (const float*)d_in[15];
    const float* D_r    = (const float*)d_in[16];
    float* out = (float*)d_out;

    cudaFuncSetAttribute(gemm_bf3, cudaFuncAttributeMaxDynamicSharedMemorySize, GEMM_SMEM);

    float* xz;
    __nv_bfloat16 *ah, *al, *w1h, *w1l, *ych, *ycl, *w2h, *w2l;
    cudaGetSymbolAddress((void**)&xz,  g_xz);
    cudaGetSymbolAddress((void**)&ah,  g_ah);
    cudaGetSymbolAddress((void**)&al,  g_al);
    cudaGetSymbolAddress((void**)&w1h, g_w1h);
    cudaGetSymbolAddress((void**)&w1l, g_w1l);
    cudaGetSymbolAddress((void**)&ych, g_ych);
    cudaGetSymbolAddress((void**)&ycl, g_ycl);
    cudaGetSymbolAddress((void**)&w2h, g_w2h);
    cudaGetSymbolAddress((void**)&w2l, g_w2l);

    // 1. split GEMM1 inputs into bf16 hi/lo
    cvt_split<<<(ROWS * DM / 4 + 255) / 256, 256>>>(x, ah, al, ROWS * DM / 4);
    cvt_split<<<(2 * DI * DM / 4 + 255) / 256, 256>>>(in_w, w1h, w1l, 2 * DI * DM / 4);
    // 2. xz = x @ in_w^T (HMMA tensor cores)
    gemm_bf3<<<dim3((2 * DI) / 128, ROWS / 128), 256, GEMM_SMEM>>>(ah, al, w1h, w1l, xz, ROWS, 2 * DI, DM);
    // 3. conv + silu, both directions
    conv_silu_kernel<<<(2 * ROWS * DI + 255) / 256, 256>>>(cw_f, cb_f, cw_r, cb_r);
    // 4. x_proj split-K + reduce (deterministic)
    xproj_splitk<<<dim3(ROWS / 32, KSPLIT, 2), 256>>>(xp_f, xp_r);
    xreduce<<<(2 * ROWS * XD + 255) / 256, 256>>>();
    // 5. dt projection + softplus
    dtproj_kernel<<<dim3(ROWS / 32, DI / 256, 2), 256>>>(dtw_f, dtb_f, dtw_r, dtb_r);
    // 6. selective scan
    scan_kernel<<<dim3(DI / 16, BB, 2), 256>>>(Alog_f, D_f, Alog_r, D_r);
    // 7. combine + gate -> bf16 hi/lo
    combine_kernel<<<(ROWS * DI + 255) / 256, 256>>>();
    // 8. out = ycomb @ out_w^T (HMMA tensor cores)
    cvt_split<<<(DM * DI / 4 + 255) / 256, 256>>>(out_w, w2h, w2l, DM * DI / 4);
    gemm_bf3<<<dim3(DM / 128, ROWS / 128), 256, GEMM_SMEM>>>(ych, ycl, w2h, w2l, out, ROWS, DM, DI);
}

// round 4
// speedup vs baseline: 1.5144x; 1.4324x over previous
#include <cuda_runtime.h>
#include <cuda_bf16.h>
#include <cstdint>
#include <cmath>

#define BB 2
#define LL 1024
#define DM 768
#define DI 1536
#define DS 16
#define DTR 48
#define XD 80            // DTR + 2*DS
#define ROWS (BB*LL)     // 2048
#define KSPLIT 6

// ================= helpers =================================================
__device__ __forceinline__ uint32_t smem_to_u32(const void* p) {
    uint32_t a;
    asm("{ .reg .u64 t; cvta.to.shared.u64 t, %1; cvt.u32.u64 %0, t; }" : "=r"(a) : "l"(p));
    return a;
}
__device__ __forceinline__ void cpasync16(uint32_t dst, const void* src) {
    asm volatile("cp.async.cg.shared.global [%0], [%1], 16;" :: "r"(dst), "l"(src));
}
#define CP_COMMIT() asm volatile("cp.async.commit_group;" ::: "memory")
#define CP_WAIT2()  asm volatile("cp.async.wait_group 2;" ::: "memory")

__device__ __forceinline__ void ldsm4(uint32_t* r, uint32_t addr) {
    asm volatile("ldmatrix.sync.aligned.m8n8.x4.shared.b16 {%0,%1,%2,%3}, [%4];"
        : "=r"(r[0]), "=r"(r[1]), "=r"(r[2]), "=r"(r[3]) : "r"(addr));
}
__device__ __forceinline__ void mma_bf16(float* c, const uint32_t* a, uint32_t b0, uint32_t b1) {
    asm volatile("mma.sync.aligned.m16n8k16.row.col.f32.bf16.bf16.f32 "
        "{%0,%1,%2,%3}, {%4,%5,%6,%7}, {%8,%9}, {%0,%1,%2,%3};"
        : "+f"(c[0]), "+f"(c[1]), "+f"(c[2]), "+f"(c[3])
        : "r"(a[0]), "r"(a[1]), "r"(a[2]), "r"(a[3]), "r"(b0), "r"(b1));
}

// ================= scratch (device globals; no allocation) =================
__device__ float g_xz[(size_t)ROWS * 2 * DI];
__device__ float g_uc[2][(size_t)ROWS * DI];
__device__ float g_xdbl[2][(size_t)ROWS * XD];
__device__ float g_xpart[2][KSPLIT][(size_t)ROWS * XD];
__device__ float g_delta[2][(size_t)ROWS * DI];
__device__ float g_y[2][(size_t)ROWS * DI];
__device__ __nv_bfloat16 g_ah[(size_t)ROWS * DM];
__device__ __nv_bfloat16 g_al[(size_t)ROWS * DM];
__device__ __nv_bfloat16 g_w1h[(size_t)(2 * DI) * DM];
__device__ __nv_bfloat16 g_w1l[(size_t)(2 * DI) * DM];
__device__ __nv_bfloat16 g_ych[(size_t)ROWS * DI];
__device__ __nv_bfloat16 g_ycl[(size_t)ROWS * DI];
__device__ __nv_bfloat16 g_w2h[(size_t)DM * DI];
__device__ __nv_bfloat16 g_w2l[(size_t)DM * DI];

// ================= fp32 -> bf16 hi/lo split ================================
__global__ void cvt_split(const float* __restrict__ s, __nv_bfloat16* __restrict__ h,
                          __nv_bfloat16* __restrict__ l, int n4)
{
    int i = blockIdx.x * blockDim.x + threadIdx.x;
    if (i >= n4) return;
    float4 v = ((const float4*)s)[i];
    __nv_bfloat16 h0 = __float2bfloat16(v.x), h1 = __float2bfloat16(v.y);
    __nv_bfloat16 h2 = __float2bfloat16(v.z), h3 = __float2bfloat16(v.w);
    __nv_bfloat16 l0 = __float2bfloat16(v.x - __bfloat162float(h0));
    __nv_bfloat16 l1 = __float2bfloat16(v.y - __bfloat162float(h1));
    __nv_bfloat16 l2 = __float2bfloat16(v.z - __bfloat162float(h2));
    __nv_bfloat16 l3 = __float2bfloat16(v.w - __bfloat162float(h3));
    ((__nv_bfloat162*)h)[2 * i]     = __nv_bfloat162(h0, h1);
    ((__nv_bfloat162*)h)[2 * i + 1] = __nv_bfloat162(h2, h3);
    ((__nv_bfloat162*)l)[2 * i]     = __nv_bfloat162(l0, l1);
    ((__nv_bfloat162*)l)[2 * i + 1] = __nv_bfloat162(l2, l3);
}

// ================= HMMA GEMM: C = A*B^T, bf16 hi/lo 3-product ==============
// 128x128 CTA tile, 512 threads, 16 warps of 32x32, 3-stage cp.async ring.
#define KT 32
#define RB 40                      // padded row length in bf16 (80 bytes)
#define TILE_B (128 * RB * 2)      // 10240 bytes per tile
#define STAGE_B (4 * TILE_B)       // Ah, Al, Bh, Bl
#define NSTAGE 3
#define GEMM_SMEM (NSTAGE * STAGE_B)  // 122880 bytes

__global__ void __launch_bounds__(512, 1) gemm_bf3(
    const __nv_bfloat16* __restrict__ Ah, const __nv_bfloat16* __restrict__ Al,
    const __nv_bfloat16* __restrict__ Bh, const __nv_bfloat16* __restrict__ Bl,
    float* __restrict__ C, int M, int N, int K)
{
    extern __shared__ char smem[];
    uint32_t sb = smem_to_u32(smem);
    int tid = threadIdx.x;
    int lane = tid & 31, wid = tid >> 5;
    int wm = (wid & 3) * 32, wn = (wid >> 2) * 32;
    int m0 = blockIdx.y * 128, n0 = blockIdx.x * 128;
    const int NC = K / KT;

    float acc[2][4][4];
#pragma unroll
    for (int a = 0; a < 2; a++)
#pragma unroll
        for (int b = 0; b < 4; b++)
#pragma unroll
            for (int c = 0; c < 4; c++) acc[a][b][c] = 0.f;

    int lr = tid >> 2, lc = tid & 3;   // 512 threads: one 16B chunk per tile
#define LOAD_STAGE(IT, S)                                                         \
    do {                                                                          \
        uint32_t stg_ = sb + (S) * STAGE_B;                                       \
        int kof_ = (IT) * KT;                                                     \
        uint32_t d_ = stg_ + lr * (RB * 2) + lc * 16;                             \
        cpasync16(d_,              Ah + (size_t)(m0 + lr) * K + kof_ + lc * 8);   \
        cpasync16(d_ + TILE_B,     Al + (size_t)(m0 + lr) * K + kof_ + lc * 8);   \
        cpasync16(d_ + 2 * TILE_B, Bh + (size_t)(n0 + lr) * K + kof_ + lc * 8);   \
        cpasync16(d_ + 3 * TILE_B, Bl + (size_t)(n0 + lr) * K + kof_ + lc * 8);   \
    } while (0)

    LOAD_STAGE(0, 0); CP_COMMIT();
    LOAD_STAGE(1, 1); CP_COMMIT();

    int stage = 2;
    for (int it = 0; it < NC; it++) {
        if (it + 2 < NC) LOAD_STAGE(it + 2, stage);
        CP_COMMIT();
        if (++stage == NSTAGE) stage = 0;
        CP_WAIT2();
        __syncthreads();
        int cs = it % NSTAGE;
        uint32_t stg = sb + cs * STAGE_B;
#pragma unroll
        for (int ks = 0; ks < 2; ks++) {
            uint32_t aH[2][4], aL[2][4];
            int arow = wm + ((lane >> 3) & 1) * 8 + (lane & 7);
            int acol = ks * 16 + (lane >> 4) * 8;
#pragma unroll
            for (int mt = 0; mt < 2; mt++) {
                uint32_t off = ((uint32_t)(arow + mt * 16) * RB + acol) * 2;
                ldsm4(aH[mt], stg + off);
                ldsm4(aL[mt], stg + TILE_B + off);
            }
            int brow = wn + (lane >> 4) * 8 + (lane & 7);
            int bcol = ks * 16 + ((lane >> 3) & 1) * 8;
#pragma unroll
            for (int p = 0; p < 2; p++) {
                uint32_t bh[4], bl[4];
                uint32_t off = ((uint32_t)(brow + p * 16) * RB + bcol) * 2;
                ldsm4(bh, stg + 2 * TILE_B + off);
                ldsm4(bl, stg + 3 * TILE_B + off);
#pragma unroll
                for (int mt = 0; mt < 2; mt++) {
                    mma_bf16(acc[mt][2 * p],     aH[mt], bh[0], bh[1]);
                    mma_bf16(acc[mt][2 * p],     aH[mt], bl[0], bl[1]);
                    mma_bf16(acc[mt][2 * p],     aL[mt], bh[0], bh[1]);
                    mma_bf16(acc[mt][2 * p + 1], aH[mt], bh[2], bh[3]);
                    mma_bf16(acc[mt][2 * p + 1], aH[mt], bl[2], bl[3]);
                    mma_bf16(acc[mt][2 * p + 1], aL[mt], bh[2], bh[3]);
                }
            }
        }
        __syncthreads();
    }

    int g = lane >> 2, tg = lane & 3;
#pragma unroll
    for (int mt = 0; mt < 2; mt++)
#pragma unroll
        for (int nt = 0; nt < 4; nt++) {
            int row = m0 + wm + mt * 16 + g;
            int col = n0 + wn + nt * 8 + tg * 2;
            *(float2*)&C[(size_t)row * N + col] =
                make_float2(acc[mt][nt][0], acc[mt][nt][1]);
            *(float2*)&C[(size_t)(row + 8) * N + col] =
                make_float2(acc[mt][nt][2], acc[mt][nt][3]);
        }
#undef LOAD_STAGE
}

// ================= causal depthwise conv + SiLU (no div/mod) ===============
// grid (DI/128, LL, BB*2), block 128
__global__ void conv_silu_kernel(const float* __restrict__ cw_f, const float* __restrict__ cb_f,
                                 const float* __restrict__ cw_r, const float* __restrict__ cb_r)
{
    int c = blockIdx.x * 128 + threadIdx.x;
    int l = blockIdx.y;
    int b = blockIdx.z & 1;
    int dir = blockIdx.z >> 1;
    const float* cw = dir ? cw_r : cw_f;
    const float* cb = dir ? cb_r : cb_f;
    float s = cb[c];
    float4 w = *(const float4*)(cw + c * 4);
    const float* base = g_xz + c;
#pragma unroll
    for (int k = 0; k < 4; k++) {
        int j = l - 3 + k;
        if (j >= 0) {
            int lsrc = dir ? (LL - 1 - j) : j;
            float wv = (k == 0) ? w.x : (k == 1) ? w.y : (k == 2) ? w.z : w.w;
            s += wv * base[(size_t)(b * LL + lsrc) * (2 * DI)];
        }
    }
    float sig = 1.f / (1.f + __expf(-s));
    g_uc[dir][(size_t)(b * LL + l) * DI + c] = s * sig;
}

// ================= x_proj split-K (deterministic) ==========================
__global__ __launch_bounds__(256) void xproj_splitk(const float* __restrict__ Wf,
                                                    const float* __restrict__ Wr)
{
    __shared__ float us[32][65];
    __shared__ float ws[80][65];
    int tid = threadIdx.x;
    int dir = blockIdx.z;
    int row0 = blockIdx.x * 32;
    int kb = blockIdx.y;
    int kbase = kb * 256;
    const float* W = dir ? Wr : Wf;
    const float* U = g_uc[dir] + (size_t)row0 * DI;
    int tx = tid & 15;
    int ty = tid >> 4;
    float acc[2][5] = {};
    for (int kc = 0; kc < 256; kc += 64) {
        int k0 = kbase + kc;
        __syncthreads();
#pragma unroll
        for (int i = 0; i < 2; i++) {
            int e = tid + i * 256;
            int r = e >> 4; int kq = (e & 15) << 2;
            float4 v = *(const float4*)(U + (size_t)r * DI + k0 + kq);
            us[r][kq + 0] = v.x; us[r][kq + 1] = v.y; us[r][kq + 2] = v.z; us[r][kq + 3] = v.w;
        }
#pragma unroll
        for (int i = 0; i < 5; i++) {
            int e = tid + i * 256;
            int r = e >> 4; int kq = (e & 15) << 2;
            float4 v = *(const float4*)(W + (size_t)r * DI + k0 + kq);
            ws[r][kq + 0] = v.x; ws[r][kq + 1] = v.y; ws[r][kq + 2] = v.z; ws[r][kq + 3] = v.w;
        }
        __syncthreads();
#pragma unroll 8
        for (int k = 0; k < 64; k++) {
            float a0 = us[ty * 2][k], a1 = us[ty * 2 + 1][k];
#pragma unroll
            for (int j = 0; j < 5; j++) {
                float w = ws[tx * 5 + j][k];
                acc[0][j] = fmaf(a0, w, acc[0][j]);
                acc[1][j] = fmaf(a1, w, acc[1][j]);
            }
        }
    }
    float* O = g_xpart[dir][kb] + (size_t)row0 * XD;
#pragma unroll
    for (int i = 0; i < 2; i++)
#pragma unroll
        for (int j = 0; j < 5; j++)
            O[(size_t)(ty * 2 + i) * XD + tx * 5 + j] = acc[i][j];
}

__global__ void xreduce()
{
    int i = blockIdx.x * blockDim.x + threadIdx.x;
    if (i >= 2 * ROWS * XD) return;
    int dir = i / (ROWS * XD);
    int off = i % (ROWS * XD);
    float s = 0.f;
#pragma unroll
    for (int k = 0; k < KSPLIT; k++) s += g_xpart[dir][k][off];
    g_xdbl[dir][off] = s;
}

// ================= dt proj + softplus (coalesced W via padded smem) ========
#define DT_SMEM (256 * 49 * 4 + 32 * DTR * 4)   // 56320 bytes
__global__ __launch_bounds__(256) void dtproj_kernel(
    const float* __restrict__ Wf, const float* __restrict__ bf,
    const float* __restrict__ Wr, const float* __restrict__ br)
{
    extern __shared__ float dsm[];
    float* wsm = dsm;                 // [256][49]
    float* xs  = dsm + 256 * 49;      // [32][48]
    int tid = threadIdx.x;
    int dir = blockIdx.z;
    int row0 = blockIdx.x * 32;
    int cbase = blockIdx.y * 256;
    const float* Wdt = dir ? Wr : Wf;
    const float* bdt = dir ? br : bf;
    // coalesced load of 256x48 weight block into padded smem
    for (int e = tid; e < 256 * DTR; e += 256) {
        int cl = e / DTR, j = e - cl * DTR;
        wsm[cl * 49 + j] = Wdt[(size_t)cbase * DTR + e];
    }
    for (int e = tid; e < 32 * DTR; e += 256) {
        int r = e / DTR, j = e - r * DTR;
        xs[r * DTR + j] = g_xdbl[dir][(size_t)(row0 + r) * XD + j];
    }
    __syncthreads();
    float w[DTR];
#pragma unroll
    for (int j = 0; j < DTR; j++) w[j] = wsm[tid * 49 + j];
    int c = cbase + tid;
    float bias = bdt[c];
    for (int r = 0; r < 32; r++) {
        float acc = bias;
#pragma unroll
        for (int j = 0; j < DTR; j++) acc = fmaf(xs[r * DTR + j], w[j], acc);
        float d = (acc > 20.f) ? acc : log1pf(__expf(acc));
        g_delta[dir][(size_t)(row0 + r) * DI + c] = d;
    }
}

// ================= selective scan ==========================================
__global__ __launch_bounds__(256) void scan_kernel(
    const float* __restrict__ Alog_f, const float* __restrict__ D_f,
    const float* __restrict__ Alog_r, const float* __restrict__ D_r)
{
    int tid = threadIdx.x;
    int dir = blockIdx.z;
    int b = blockIdx.y;
    int c = blockIdx.x * 16 + (tid >> 4);
    int s = tid & 15;
    const float* Alog = dir ? Alog_r : Alog_f;
    const float* Dp   = dir ? D_r : D_f;
    float a  = -__expf(Alog[c * DS + s]);
    float Dv = Dp[c];
    const float* dlt = g_delta[dir] + (size_t)(b * LL) * DI + c;
    const float* uu  = g_uc[dir]    + (size_t)(b * LL) * DI + c;
    const float* xd  = g_xdbl[dir]  + (size_t)(b * LL) * XD;
    float* yo        = g_y[dir]     + (size_t)(b * LL) * DI + c;
    float h = 0.f;
#pragma unroll 4
    for (int t = 0; t < LL; t++) {
        float d  = dlt[(size_t)t * DI];
        float uv = uu[(size_t)t * DI];
        float Bv = xd[(size_t)t * XD + DTR + s];
        float Cv = xd[(size_t)t * XD + DTR + DS + s];
        float dA = __expf(d * a);
        h = fmaf(dA, h, d * Bv * uv);
        float p = h * Cv;
        p += __shfl_xor_sync(0xffffffffu, p, 1);
        p += __shfl_xor_sync(0xffffffffu, p, 2);
        p += __shfl_xor_sync(0xffffffffu, p, 4);
        p += __shfl_xor_sync(0xffffffffu, p, 8);
        if (s == 0) yo[(size_t)t * DI] = fmaf(uv, Dv, p);
    }
}

// ================= combine + gate -> bf16 hi/lo ============================
__global__ void combine_kernel()
{
    int c = blockIdx.x * 256 + threadIdx.x;
    int l = blockIdx.y;
    int b = blockIdx.z;
    size_t idx = (size_t)(b * LL + l) * DI + c;
    float yf = g_y[0][idx];
    float yr = g_y[1][(size_t)(b * LL + (LL - 1 - l)) * DI + c];
    float z  = g_xz[(size_t)(b * LL + l) * (2 * DI) + DI + c];
    float sig = 1.f / (1.f + __expf(-z));
    float v = (yf + yr) * (z * sig);
    __nv_bfloat16 h = __float2bfloat16(v);
    g_ych[idx] = h;
    g_ycl[idx] = __float2bfloat16(v - __bfloat162float(h));
}

// ================= launch ==================================================
extern "C" void kernel_launch(void* const* d_in, const int* in_sizes, int n_in,
                              void* d_out, int out_size)
{
    const float* x      = (const float*)d_in[0];
    const float* in_w   = (const float*)d_in[1];
    const float* out_w  = (const float*)d_in[2];
    const float* cw_f   = (const float*)d_in[3];
    const float* cb_f   = (const float*)d_in[4];
    const float* xp_f   = (const float*)d_in[5];
    const float* dtw_f  = (const float*)d_in[6];
    const float* dtb_f  = (const float*)d_in[7];
    const float* Alog_f = (const float*)d_in[8];
    const float* D_f    = (const float*)d_in[9];
    const float* cw_r   = (const float*)d_in[10];
    const float* cb_r   = (const float*)d_in[11];
    const float* xp_r   = (const float*)d_in[12];
    const float* dtw_r  = (const float*)d_in[13];
    const float* dtb_r  = (const float*)d_in[14];
    const float* Alog_r = (const float*)d_in[15];
    const float* D_r    = (const float*)d_in[16];
    float* out = (float*)d_out;

    cudaFuncSetAttribute(gemm_bf3, cudaFuncAttributeMaxDynamicSharedMemorySize, GEMM_SMEM);
    cudaFuncSetAttribute(dtproj_kernel, cudaFuncAttributeMaxDynamicSharedMemorySize, DT_SMEM);

    float* xz;
    __nv_bfloat16 *ah, *al, *w1h, *w1l, *ych, *ycl, *w2h, *w2l;
    cudaGetSymbolAddress((void**)&xz,  g_xz);
    cudaGetSymbolAddress((void**)&ah,  g_ah);
    cudaGetSymbolAddress((void**)&al,  g_al);
    cudaGetSymbolAddress((void**)&w1h, g_w1h);
    cudaGetSymbolAddress((void**)&w1l, g_w1l);
    cudaGetSymbolAddress((void**)&ych, g_ych);
    cudaGetSymbolAddress((void**)&ycl, g_ycl);
    cudaGetSymbolAddress((void**)&w2h, g_w2h);
    cudaGetSymbolAddress((void**)&w2l, g_w2l);

    // 1. split GEMM1 inputs into bf16 hi/lo
    cvt_split<<<(ROWS * DM / 4 + 255) / 256, 256>>>(x, ah, al, ROWS * DM / 4);
    cvt_split<<<(2 * DI * DM / 4 + 255) / 256, 256>>>(in_w, w1h, w1l, 2 * DI * DM / 4);
    // 2. xz = x @ in_w^T
    gemm_bf3<<<dim3((2 * DI) / 128, ROWS / 128), 512, GEMM_SMEM>>>(ah, al, w1h, w1l, xz, ROWS, 2 * DI, DM);
    // 3. conv + silu
    conv_silu_kernel<<<dim3(DI / 128, LL, BB * 2), 128>>>(cw_f, cb_f, cw_r, cb_r);
    // 4. x_proj split-K + reduce
    xproj_splitk<<<dim3(ROWS / 32, KSPLIT, 2), 256>>>(xp_f, xp_r);
    xreduce<<<(2 * ROWS * XD + 255) / 256, 256>>>();
    // 5. dt projection + softplus
    dtproj_kernel<<<dim3(ROWS / 32, DI / 256, 2), 256, DT_SMEM>>>(dtw_f, dtb_f, dtw_r, dtb_r);
    // 6. selective scan
    scan_kernel<<<dim3(DI / 16, BB, 2), 256>>>(Alog_f, D_f, Alog_r, D_r);
    // 7. combine + gate -> bf16 hi/lo
    combine_kernel<<<dim3(DI / 256, LL, BB), 256>>>();
    // 8. out = ycomb @ out_w^T
    cvt_split<<<(DM * DI / 4 + 255) / 256, 256>>>(out_w, w2h, w2l, DM * DI / 4);
    gemm_bf3<<<dim3(DM / 128, ROWS / 128), 512, GEMM_SMEM>>>(ych, ycl, w2h, w2l, out, ROWS, DM, DI);
}